// round 4
// baseline (speedup 1.0000x reference)
#include <cuda_runtime.h>

#define AD 512
#define BB 16
#define HH 8
#define CROSS_C 359   // A - int(A*0.3) = 512 - 153

// ---------------- scratch (static device globals; no allocs) ----------------
__device__ float g_QpT[BB * AD * AD];   // QpT[b][i][j] = Qp[b][j][i]
__device__ float g_KpT[BB * AD * AD];   // KpT[b][k][j] = Kp[b][j][k]
__device__ float g_am0[BB * AD * AD];   // am0[b][i][k]
__device__ float g_Vp[BB * AD];
__device__ float g_att[BB * HH * AD];

// ---------------- threefry2x32 (20 rounds, JAX-compatible) ----------------
__device__ __forceinline__ void tf2x32(unsigned k0, unsigned k1,
                                       unsigned x0, unsigned x1,
                                       unsigned &o0, unsigned &o1) {
    unsigned k2 = k0 ^ k1 ^ 0x1BD11BDAu;
    x0 += k0; x1 += k1;
#define TFR(r) { x0 += x1; x1 = __funnelshift_l(x1, x1, r); x1 ^= x0; }
    TFR(13) TFR(15) TFR(26) TFR(6)   x0 += k1; x1 += k2 + 1u;
    TFR(17) TFR(29) TFR(16) TFR(24)  x0 += k2; x1 += k0 + 2u;
    TFR(13) TFR(15) TFR(26) TFR(6)   x0 += k0; x1 += k1 + 3u;
    TFR(17) TFR(29) TFR(16) TFR(24)  x0 += k1; x1 += k2 + 4u;
    TFR(13) TFR(15) TFR(26) TFR(6)   x0 += k2; x1 += k0 + 5u;
#undef TFR
    o0 = x0; o1 = x1;
}

__device__ __forceinline__ float bits_to_unit(unsigned bits) {
    return __uint_as_float((bits >> 9) | 0x3f800000u) - 1.0f;
}

// ---------------- tf32 helpers ----------------
__device__ __forceinline__ void split_tf32(float x, unsigned &hi, unsigned &lo) {
    unsigned h;
    asm("cvt.rna.tf32.f32 %0, %1;" : "=r"(h) : "f"(x));
    float r = x - __uint_as_float(h);
    unsigned l;
    asm("cvt.rna.tf32.f32 %0, %1;" : "=r"(l) : "f"(r));
    hi = h; lo = l;
}

__device__ __forceinline__ void mma_tf32(float* c, const unsigned* a, const unsigned* b) {
    asm volatile(
        "mma.sync.aligned.m16n8k8.row.col.f32.tf32.tf32.f32 "
        "{%0,%1,%2,%3}, {%4,%5,%6,%7}, {%8,%9}, {%0,%1,%2,%3};"
        : "+f"(c[0]), "+f"(c[1]), "+f"(c[2]), "+f"(c[3])
        : "r"(a[0]), "r"(a[1]), "r"(a[2]), "r"(a[3]), "r"(b[0]), "r"(b[1]));
}

// ---------------- TN GEMM core: C[m][n] = scale*sum_k A[m][k]*B[n][k] + bias[m]
// BM=BN=128, BK=8, 256 threads (8 warps 4x2), warp tile 32x64, 3xTF32.
// tf32 (hi,lo) precomputed ONCE per element into smem as uint2.
__device__ __forceinline__ void gemm_tn_core(const float* __restrict__ A,
                                             const float* __restrict__ B,
                                             float* __restrict__ C,
                                             const float* __restrict__ bias,
                                             float scale) {
    __shared__ uint2 As[2][128][10];   // [stage][row][k] {hi,lo}, pad to 10
    __shared__ uint2 Bs[2][128][10];
    int tid = threadIdx.x;
    int lane = tid & 31, wid = tid >> 5;
    int wm = wid & 3, wn = wid >> 2;
    int m0 = blockIdx.y * 128, n0 = blockIdx.x * 128;
    int qr = lane >> 2, qc = lane & 3;

    float acc[2][8][4];
#pragma unroll
    for (int mi = 0; mi < 2; mi++)
#pragma unroll
        for (int ni = 0; ni < 8; ni++)
#pragma unroll
            for (int e = 0; e < 4; e++) acc[mi][ni][e] = 0.f;

    int lr = tid >> 1;            // row 0..127
    int lc = (tid & 1) * 4;       // k 0 or 4
    const float* Ag = A + (size_t)(m0 + lr) * AD + lc;
    const float* Bg = B + (size_t)(n0 + lr) * AD + lc;

#define STORE_SPLIT(Sarr, sn, f4)                                   \
    {                                                               \
        uint4 p0, p1;                                               \
        split_tf32((f4).x, p0.x, p0.y);                             \
        split_tf32((f4).y, p0.z, p0.w);                             \
        split_tf32((f4).z, p1.x, p1.y);                             \
        split_tf32((f4).w, p1.z, p1.w);                             \
        *(uint4*)&Sarr[sn][lr][lc]     = p0;                        \
        *(uint4*)&Sarr[sn][lr][lc + 2] = p1;                        \
    }

    {   // prologue: stage 0
        float4 a0 = *(const float4*)Ag;
        float4 b0 = *(const float4*)Bg;
        STORE_SPLIT(As, 0, a0)
        STORE_SPLIT(Bs, 0, b0)
    }
    __syncthreads();

    const int NIT = AD / 8;     // 64
    for (int it = 0; it < NIT; ++it) {
        int s = it & 1;
        float4 anx, bnx;
        if (it + 1 < NIT) {
            anx = *(const float4*)(Ag + (it + 1) * 8);
            bnx = *(const float4*)(Bg + (it + 1) * 8);
        }

        // ---- mma on stage s ----
        uint2 afr[2][4];
#pragma unroll
        for (int mi = 0; mi < 2; mi++)
#pragma unroll
            for (int e = 0; e < 4; e++)
                afr[mi][e] = As[s][wm * 32 + mi * 16 + qr + (e & 1) * 8]
                               [qc + (e >> 1) * 4];
#pragma unroll
        for (int half = 0; half < 2; half++) {
            uint2 bfr[4][2];
#pragma unroll
            for (int ni = 0; ni < 4; ni++)
#pragma unroll
                for (int e = 0; e < 2; e++)
                    bfr[ni][e] = Bs[s][wn * 64 + (half * 4 + ni) * 8 + qr]
                                   [qc + e * 4];
#pragma unroll
            for (int mi = 0; mi < 2; mi++) {
                unsigned ah[4] = {afr[mi][0].x, afr[mi][1].x, afr[mi][2].x, afr[mi][3].x};
                unsigned al[4] = {afr[mi][0].y, afr[mi][1].y, afr[mi][2].y, afr[mi][3].y};
#pragma unroll
                for (int ni = 0; ni < 4; ni++) {
                    unsigned bh[2] = {bfr[ni][0].x, bfr[ni][1].x};
                    unsigned bl[2] = {bfr[ni][0].y, bfr[ni][1].y};
                    float* c = acc[mi][half * 4 + ni];
                    mma_tf32(c, ah, bh);
                    mma_tf32(c, ah, bl);
                    mma_tf32(c, al, bh);
                }
            }
        }

        if (it + 1 < NIT) {
            STORE_SPLIT(As, s ^ 1, anx)
            STORE_SPLIT(Bs, s ^ 1, bnx)
        }
        __syncthreads();
    }
#undef STORE_SPLIT

    // epilogue
#pragma unroll
    for (int mi = 0; mi < 2; mi++) {
        int r0 = m0 + wm * 32 + mi * 16 + qr;
        float b0 = 0.f, b1 = 0.f;
        if (bias) { b0 = __ldg(bias + r0); b1 = __ldg(bias + r0 + 8); }
#pragma unroll
        for (int ni = 0; ni < 8; ni++) {
            int c0 = n0 + wn * 64 + ni * 8 + qc * 2;
            float2 v0, v1;
            v0.x = acc[mi][ni][0] * scale + b0;
            v0.y = acc[mi][ni][1] * scale + b0;
            v1.x = acc[mi][ni][2] * scale + b1;
            v1.y = acc[mi][ni][3] * scale + b1;
            *(float2*)&C[(size_t)r0 * AD + c0] = v0;
            *(float2*)&C[(size_t)(r0 + 8) * AD + c0] = v1;
        }
    }
}

// merged Q/K projection: QpT[i][j] = sum_t W[i,t]*X[j,t] + bias[i]
__global__ __launch_bounds__(256, 2) void proj_kernel(
    const float* __restrict__ Q, const float* __restrict__ K,
    const float* __restrict__ WQw, const float* __restrict__ WQb,
    const float* __restrict__ WKw, const float* __restrict__ WKb) {
    int z = blockIdx.z;
    int b = z & (BB - 1);
    int sel = z >> 4;
    const float* A = sel ? WKw : WQw;
    const float* X = (sel ? K : Q) + (size_t)b * AD * AD;
    float* C = (sel ? g_KpT : g_QpT) + (size_t)b * AD * AD;
    const float* bias = sel ? WKb : WQb;
    gemm_tn_core(A, X, C, bias, 1.0f);
}

// scores: am0[i][k] = (1/sqrt8) * sum_j QpT[i][j]*KpT[k][j]
__global__ __launch_bounds__(256, 2) void scores_kernel() {
    int b = blockIdx.z;
    gemm_tn_core(g_QpT + (size_t)b * AD * AD, g_KpT + (size_t)b * AD * AD,
                 g_am0 + (size_t)b * AD * AD, nullptr, 0.3535533905932738f);
}

// ---------------- Vp = V @ WV^T + b  (16x512, tiny) ----------------
__global__ __launch_bounds__(256) void vproj(const float* __restrict__ V,
                                             const float* __restrict__ Ww,
                                             const float* __restrict__ Wb) {
    int b = blockIdx.x;
    int wid = threadIdx.x >> 5, lane = threadIdx.x & 31;
    const float* vr = V + b * AD;
#pragma unroll
    for (int ii = 0; ii < 4; ii++) {
        int i = blockIdx.y * 32 + wid * 4 + ii;
        const float* wr = Ww + (size_t)i * AD;
        float s = 0.f;
        for (int t = lane; t < AD; t += 32) s += vr[t] * wr[t];
#pragma unroll
        for (int o = 16; o; o >>= 1) s += __shfl_xor_sync(~0u, s, o);
        if (lane == 0) g_Vp[b * AD + i] = s + Wb[i];
    }
}

// ---------------- attn: warp-per-row, specialized branches ----------------
// mutate: v = am0[b,i,k] * max(0.7, u*0.6+0.7); softmax (no max pass); dot Vp
struct MutP { unsigned km0, km1; };

__global__ __launch_bounds__(256) void attn_mut(MutP P) {
    int row = blockIdx.x * 8 + (threadIdx.x >> 5);   // (b*8+h)*512 + i
    int lane = threadIdx.x & 31;
    int i = row & (AD - 1);
    int b = row >> 12;
    const float* am = g_am0 + (size_t)b * AD * AD + (size_t)i * AD;
    const float* Vb = g_Vp + b * AD;
    unsigned base = ((unsigned)row) << 9;
    float s = 0.f, d = 0.f;
#pragma unroll 4
    for (int q = 0; q < 16; q++) {
        int k = lane + q * 32;
        unsigned o0, o1;
        tf2x32(P.km0, P.km1, 0u, base + (unsigned)k, o0, o1);
        float u = bits_to_unit(o0 ^ o1);
        float m = fmaxf(0.7f, fmaf(u, 0.6f, 0.7f));
        float e = __expf(am[k] * m);
        s += e;
        d += e * Vb[k];
    }
#pragma unroll
    for (int o = 16; o; o >>= 1) {
        s += __shfl_xor_sync(~0u, s, o);
        d += __shfl_xor_sync(~0u, d, o);
    }
    if (lane == 0) g_att[row] = d / s;     // row == b*4096 + h*512 + i
}

struct CrossP { unsigned short r1[BB * HH]; unsigned short r2[BB * HH]; };

__global__ __launch_bounds__(256) void attn_cross(CrossP P) {
    int row = blockIdx.x * 8 + (threadIdx.x >> 5);
    int lane = threadIdx.x & 31;
    int i = row & (AD - 1);
    int bh = row >> 9;                      // b*8+h
    int b = row >> 12;
    int r1 = P.r1[bh], r2 = P.r2[bh];
    int tsrc = i;
    if (i == r1) tsrc = r2;
    else if (i == r2) tsrc = r1;
    const float* amb = g_am0 + (size_t)b * AD * AD;
    const float* ami = amb + (size_t)i * AD;
    const float* amt = amb + (size_t)tsrc * AD;
    const float* Vb = g_Vp + b * AD;
    float s = 0.f, d = 0.f;
#pragma unroll
    for (int q = 0; q < 16; q++) {
        int k = lane + q * 32;
        float v = (k >= CROSS_C) ? amt[k] : ami[k];
        float e = __expf(v);
        s += e;
        d += e * Vb[k];
    }
#pragma unroll
    for (int o = 16; o; o >>= 1) {
        s += __shfl_xor_sync(~0u, s, o);
        d += __shfl_xor_sync(~0u, d, o);
    }
    if (lane == 0) g_att[row] = d / s;
}

// ---------------- out = att(16,4096) @ WO_w(512,4096)^T + WO_b ----------------
__global__ __launch_bounds__(256) void outproj(const float* __restrict__ Ww,
                                               const float* __restrict__ Wb,
                                               float* __restrict__ out) {
    __shared__ float arow[HH * AD];   // 16 KB
    int b = blockIdx.x;
    for (int m = threadIdx.x; m < HH * AD; m += 256)
        arow[m] = g_att[b * HH * AD + m];
    __syncthreads();
    int wid = threadIdx.x >> 5, lane = threadIdx.x & 31;
    const float4* ar = (const float4*)arow;
#pragma unroll
    for (int l = 0; l < 8; l++) {
        int n = blockIdx.y * 64 + wid * 8 + l;
        const float4* wr = (const float4*)(Ww + (size_t)n * (HH * AD));
        float s = 0.f;
        for (int m = lane; m < (HH * AD) / 4; m += 32) {
            float4 w = wr[m], a = ar[m];
            s += w.x * a.x + w.y * a.y + w.z * a.z + w.w * a.w;
        }
#pragma unroll
        for (int o = 16; o; o >>= 1) s += __shfl_xor_sync(~0u, s, o);
        if (lane == 0) out[b * AD + n] = s + Wb[n];
    }
}

// ---------------- host-side threefry (constant key 42; deterministic) -------
static inline unsigned h_rotl(unsigned x, int r) { return (x << r) | (x >> (32 - r)); }
static void h_tf2x32(unsigned k0, unsigned k1, unsigned x0, unsigned x1,
                     unsigned &o0, unsigned &o1) {
    unsigned k2 = k0 ^ k1 ^ 0x1BD11BDAu;
    x0 += k0; x1 += k1;
#define HTFR(r) { x0 += x1; x1 = h_rotl(x1, r); x1 ^= x0; }
    HTFR(13) HTFR(15) HTFR(26) HTFR(6)   x0 += k1; x1 += k2 + 1u;
    HTFR(17) HTFR(29) HTFR(16) HTFR(24)  x0 += k2; x1 += k0 + 2u;
    HTFR(13) HTFR(15) HTFR(26) HTFR(6)   x0 += k0; x1 += k1 + 3u;
    HTFR(17) HTFR(29) HTFR(16) HTFR(24)  x0 += k1; x1 += k2 + 4u;
    HTFR(13) HTFR(15) HTFR(26) HTFR(6)   x0 += k2; x1 += k0 + 5u;
#undef HTFR
    o0 = x0; o1 = x1;
}
static inline float h_bits_to_unit(unsigned bits) {
    union { unsigned u; float f; } c;
    c.u = (bits >> 9) | 0x3f800000u;
    return c.f - 1.0f;
}

// ---------------- launch ----------------
extern "C" void kernel_launch(void* const* d_in, const int* in_sizes, int n_in,
                              void* d_out, int out_size) {
    const float* Q   = (const float*)d_in[0];
    const float* K   = (const float*)d_in[1];
    const float* V   = (const float*)d_in[2];
    const float* WQw = (const float*)d_in[3];
    const float* WQb = (const float*)d_in[4];
    const float* WKw = (const float*)d_in[5];
    const float* WKb = (const float*)d_in[6];
    const float* WVw = (const float*)d_in[7];
    const float* WVb = (const float*)d_in[8];
    const float* WOw = (const float*)d_in[9];
    const float* WOb = (const float*)d_in[10];
    float* out = (float*)d_out;

    // host RNG setup (pure constants from key 42)
    unsigned kp0, kp1, km0, km1, ka0, ka1, kb0, kb1;
    h_tf2x32(0u, 42u, 0u, 0u, kp0, kp1);
    h_tf2x32(0u, 42u, 0u, 1u, km0, km1);
    h_tf2x32(0u, 42u, 0u, 2u, ka0, ka1);
    h_tf2x32(0u, 42u, 0u, 3u, kb0, kb1);
    unsigned b0, b1;
    h_tf2x32(kp0, kp1, 0u, 0u, b0, b1);
    int mutate = (h_bits_to_unit(b0 ^ b1) <= 0.6f) ? 1 : 0;

    proj_kernel<<<dim3(4, 4, 32), 256>>>(Q, K, WQw, WQb, WKw, WKb);
    vproj<<<dim3(BB, 16), 256>>>(V, WVw, WVb);
    scores_kernel<<<dim3(4, 4, 16), 256>>>();

    if (mutate) {
        MutP P; P.km0 = km0; P.km1 = km1;
        attn_mut<<<BB * HH * AD / 8, 256>>>(P);
    } else {
        CrossP P;
        unsigned s0, s1, l0, l1;
        h_tf2x32(ka0, ka1, 0u, 1u, s0, s1);
        for (int t = 0; t < BB * HH; t++) {
            h_tf2x32(s0, s1, 0u, (unsigned)t, l0, l1);
            P.r1[t] = (unsigned short)((l0 ^ l1) & (AD - 1u));
        }
        h_tf2x32(kb0, kb1, 0u, 1u, s0, s1);
        for (int t = 0; t < BB * HH; t++) {
            h_tf2x32(s0, s1, 0u, (unsigned)t, l0, l1);
            P.r2[t] = (unsigned short)((l0 ^ l1) & (AD - 1u));
        }
        attn_cross<<<BB * HH * AD / 8, 256>>>(P);
    }
    outproj<<<dim3(BB, 8), 256>>>(WOw, WOb, out);
}